// round 4
// baseline (speedup 1.0000x reference)
#include <cuda_runtime.h>

// cost = 0.5 * sum_n x_n^T C_n x_n
// N_BLOCKS = 8192, BLOCK = 64
// d_in[0] = x        [524288] fp32
// d_in[1] = C_blocks [8192*64*64] fp32
// d_out   = [1] fp32

#define N_BLOCKS 8192
#define BLK 64
#define GRID 1024                 // 8 contiguous blocks per CTA -> flat 128KB stream
#define BPC  (N_BLOCKS / GRID)    // 8

__device__ double g_acc;            // zero-initialized at module load
__device__ unsigned int g_count;    // zero-initialized

__global__ __launch_bounds__(256) void quadform_kernel(
    const float* __restrict__ x,
    const float* __restrict__ C,
    float* __restrict__ out)
{
    __shared__ float xs[BPC * BLK];    // 2 KB: x for all 8 blocks of this CTA
    __shared__ float warp_sums[8];

    const int t    = threadIdx.x;      // 0..255
    const int lane = t & 31;
    const int wid  = t >> 5;
    const int bid  = blockIdx.x;

    // Preload x for the CTA's 8 contiguous blocks (512 floats = 128 float4).
    if (t < 128) {
        reinterpret_cast<float4*>(xs)[t] =
            reinterpret_cast<const float4*>(x)[bid * (BPC * BLK / 4) + t];
    }
    __syncthreads();

    // CTA's flat C window: 8 blocks * 1024 float4 = 8192 float4, contiguous.
    const float4* C4 = reinterpret_cast<const float4*>(C) + (size_t)bid * (BPC * BLK * BLK / 4);

    float acc0 = 0.f, acc1 = 0.f;

    // Prologue: loads for k = 0.
    float4 a0 = C4[0 * 256 + t];
    float4 a1 = C4[1 * 256 + t];
    float4 a2 = C4[2 * 256 + t];
    float4 a3 = C4[3 * 256 + t];

    #pragma unroll
    for (int k = 0; k < BPC; k++) {
        float4 b0, b1, b2, b3;
        if (k < BPC - 1) {
            // Prefetch next block's 4 loads BEFORE computing on current data.
            const float4* N4 = C4 + (k + 1) * 1024;
            b0 = N4[0 * 256 + t];
            b1 = N4[1 * 256 + t];
            b2 = N4[2 * 256 + t];
            b3 = N4[3 * 256 + t];
        }

        const float*  xb  = xs + k * BLK;
        const float4* xb4 = reinterpret_cast<const float4*>(xb);

        {   const int fp = 0 * 256 + t;   // row = fp>>4, col4 = fp&15
            const float4 xc = xb4[fp & 15];
            acc0 += xb[fp >> 4] * (a0.x * xc.x + a0.y * xc.y + a0.z * xc.z + a0.w * xc.w);
        }
        {   const int fp = 1 * 256 + t;
            const float4 xc = xb4[fp & 15];
            acc1 += xb[fp >> 4] * (a1.x * xc.x + a1.y * xc.y + a1.z * xc.z + a1.w * xc.w);
        }
        {   const int fp = 2 * 256 + t;
            const float4 xc = xb4[fp & 15];
            acc0 += xb[fp >> 4] * (a2.x * xc.x + a2.y * xc.y + a2.z * xc.z + a2.w * xc.w);
        }
        {   const int fp = 3 * 256 + t;
            const float4 xc = xb4[fp & 15];
            acc1 += xb[fp >> 4] * (a3.x * xc.x + a3.y * xc.y + a3.z * xc.z + a3.w * xc.w);
        }

        if (k < BPC - 1) {
            a0 = b0; a1 = b1; a2 = b2; a3 = b3;   // rotation (dissolves under full unroll)
        }
    }

    float acc = acc0 + acc1;

    // Intra-CTA reduction
    #pragma unroll
    for (int off = 16; off > 0; off >>= 1)
        acc += __shfl_down_sync(0xFFFFFFFFu, acc, off);
    if (lane == 0) warp_sums[wid] = acc;
    __syncthreads();

    if (wid == 0) {
        float s = (lane < 8) ? warp_sums[lane] : 0.f;
        #pragma unroll
        for (int off = 4; off > 0; off >>= 1)
            s += __shfl_down_sync(0xFFFFFFFFu, s, off);

        if (lane == 0) {
            atomicAdd(&g_acc, (double)s);
            __threadfence();
            unsigned int done = atomicAdd(&g_count, 1u);
            if (done == GRID - 1) {
                // Last CTA: read full sum, write output, reset for next replay.
                double total = atomicAdd(&g_acc, 0.0);
                out[0] = (float)(0.5 * total);
                g_acc = 0.0;
                g_count = 0u;
                __threadfence();
            }
        }
    }
}

extern "C" void kernel_launch(void* const* d_in, const int* in_sizes, int n_in,
                              void* d_out, int out_size) {
    const float* x = (const float*)d_in[0];
    const float* C = (const float*)d_in[1];
    float* out = (float*)d_out;

    quadform_kernel<<<GRID, 256>>>(x, C, out);
}

// round 10
// speedup vs baseline: 1.0045x; 1.0045x over previous
#include <cuda_runtime.h>
#include <cuda_pipeline_primitives.h>
#include <cstdint>

// cost = 0.5 * sum_n x_n^T C_n x_n
// N_BLOCKS = 8192, BLOCK = 64
// d_in[0] = x [524288] fp32, d_in[1] = C_blocks [8192*64*64] fp32, d_out = [1] fp32

#define N_BLOCKS 8192
#define BLK 64
#define GRID 888                 // 148 SMs * 6 resident CTAs -> one balanced wave
#define S 2                      // double-buffered cp.async pipeline
#define TILE_FLOATS (BLK * BLK)  // 4096 floats = 1024 float4 = 16 KB
#define MAXB 10                  // ceil(8192/888)

__device__ double g_acc;            // zero-initialized at module load
__device__ unsigned int g_count;

__global__ __launch_bounds__(256, 6) void quadform_kernel(
    const float* __restrict__ x,
    const float* __restrict__ C,
    float* __restrict__ out)
{
    __shared__ __align__(16) float sbuf[S * TILE_FLOATS];  // 32 KB
    __shared__ float xs[MAXB * BLK];                        // 2.5 KB
    __shared__ float warp_sums[8];

    const int t    = threadIdx.x;      // 0..255
    const int lane = t & 31;
    const int wid  = t >> 5;
    const int bid  = blockIdx.x;

    // Contiguous balanced span of blocks for this CTA (9 or 10 blocks).
    const int n0 = (bid * N_BLOCKS) / GRID;
    const int n1 = ((bid + 1) * N_BLOCKS) / GRID;
    const int nb = n1 - n0;

    const float4* Cg = reinterpret_cast<const float4*>(C);

    // Prologue: issue cp.async for the first S stages.
    // One 16KB tile = 1024 float4; each thread copies 4 (indices j*256 + t).
    #pragma unroll
    for (int s = 0; s < S; s++) {
        if (s < nb) {
            const size_t gbase = (size_t)(n0 + s) * (TILE_FLOATS / 4);
            float4* dst = reinterpret_cast<float4*>(sbuf + s * TILE_FLOATS);
            #pragma unroll
            for (int j = 0; j < 4; j++)
                __pipeline_memcpy_async(&dst[j * 256 + t], &Cg[gbase + j * 256 + t], 16);
        }
        __pipeline_commit();
    }

    // Preload x for the whole span (overlaps with cp.async flight).
    for (int i = t; i < nb * 16; i += 256) {
        reinterpret_cast<float4*>(xs)[i] =
            reinterpret_cast<const float4*>(x)[n0 * 16 + i];
    }

    float acc0 = 0.f, acc1 = 0.f;

    for (int k = 0; k < nb; k++) {
        const int s = k % S;

        if (k + 1 < nb) __pipeline_wait_prior(S - 1);
        else            __pipeline_wait_prior(0);
        __syncthreads();   // all threads' copies for stage k now visible

        const float*  xb   = xs + k * BLK;
        const float4* xb4  = reinterpret_cast<const float4*>(xb);
        const float4* buf4 = reinterpret_cast<const float4*>(sbuf + s * TILE_FLOATS);
        const float4  xc   = xb4[t & 15];   // (p*256+t)&15 == t&15: constant

        // CORRECT consumer: 1024 float4 per tile -> 4 passes of 256 threads.
        // fp = p*256 + t in [0,1024); row = fp>>4 in [0,64).
        #pragma unroll
        for (int p = 0; p < 4; p++) {
            const int    fp = p * 256 + t;
            const float4 v  = buf4[fp];
            const float  xr = xb[fp >> 4];
            const float  d  = v.x * xc.x + v.y * xc.y + v.z * xc.z + v.w * xc.w;
            if (p & 1) acc1 += xr * d; else acc0 += xr * d;
        }

        __syncthreads();   // everyone done reading buf[s] before refilling it

        if (k + S < nb) {
            const size_t gbase = (size_t)(n0 + k + S) * (TILE_FLOATS / 4);
            float4* dst = reinterpret_cast<float4*>(sbuf + s * TILE_FLOATS);
            #pragma unroll
            for (int j = 0; j < 4; j++)
                __pipeline_memcpy_async(&dst[j * 256 + t], &Cg[gbase + j * 256 + t], 16);
            __pipeline_commit();
        } else {
            __pipeline_commit();   // uniform group accounting in the tail
        }
    }

    float acc = acc0 + acc1;

    // Intra-CTA reduction
    #pragma unroll
    for (int off = 16; off > 0; off >>= 1)
        acc += __shfl_down_sync(0xFFFFFFFFu, acc, off);
    if (lane == 0) warp_sums[wid] = acc;
    __syncthreads();

    if (wid == 0) {
        float v = (lane < 8) ? warp_sums[lane] : 0.f;
        #pragma unroll
        for (int off = 4; off > 0; off >>= 1)
            v += __shfl_down_sync(0xFFFFFFFFu, v, off);

        if (lane == 0) {
            atomicAdd(&g_acc, (double)v);
            __threadfence();
            unsigned int done = atomicAdd(&g_count, 1u);
            if (done == GRID - 1) {
                double total = atomicAdd(&g_acc, 0.0);
                out[0] = (float)(0.5 * total);
                g_acc = 0.0;
                g_count = 0u;
                __threadfence();
            }
        }
    }
}

extern "C" void kernel_launch(void* const* d_in, const int* in_sizes, int n_in,
                              void* d_out, int out_size) {
    const float* x = (const float*)d_in[0];
    const float* C = (const float*)d_in[1];
    float* out = (float*)d_out;

    quadform_kernel<<<GRID, 256>>>(x, C, out);
}